// round 8
// baseline (speedup 1.0000x reference)
#include <cuda_runtime.h>

#define NWARM 365
#define PFD 6   // prefetch depth (register pipeline of future timesteps)

// PARAM_RANGES lo/hi, order: KC,PCTIM,ADIMP,UZTWM,UZFWM,LZTWM,LZFSM,LZFPM,RSERV,
// PFREE,RIVA,ZPERC,REXP,UZK,LZSK,LZPK,CI,CGS,CGP,KE,XE
__constant__ float c_lo[21] = {0.1f, 0.0f, 0.0f, 10.0f, 10.0f, 50.0f, 10.0f, 50.0f,
                               0.0f, 0.0f, 0.0f, 5.0f, 1.0f, 0.1f, 0.01f, 0.001f,
                               0.5f, 0.95f, 0.98f, 0.0f, 0.0f};
__constant__ float c_hi[21] = {1.2f, 0.1f, 0.3f, 100.0f, 100.0f, 400.0f, 100.0f, 1000.0f,
                               0.3f, 0.5f, 0.1f, 350.0f, 4.0f, 0.5f, 0.35f, 0.05f,
                               0.9f, 0.998f, 0.998f, 1.0f, 0.5f};

// Loop-invariant per-basin parameter pack (only what the step body uses).
struct Prm {
    float kc, pctim, adimp;
    float uztwm, uzfwm, lztwm, lzfsm, lzfpm;
    float pfree, riva, zperc, rexp, uzk, lzsk, lzpk;
    float ci, cgs, cgp;
    float inv_uztwm, inv_sum_utlt, inv_lztwm, sum_uzm;
    float pbase_div_uzfwm, sum_lzm, inv_sum_lzm, sum_lzf, cf2;
    float inv_lzfpm, inv_lzfsm, parea;
    float omlzsk, omlzpk, gi, ggs, ggp;
    float c1, c2, c3;
};

struct St {
    float auztw, alztw, uztw, uzfw, lztw, lzfs, lzfp;
    float qs, qi, qgs, qgp, mq;
};

__device__ __forceinline__ void load_prm(const float* __restrict__ raw, int b, Prm& P) {
    float pr[21];
#pragma unroll
    for (int i = 0; i < 21; ++i)
        pr[i] = fmaf(raw[b * 21 + i], c_hi[i] - c_lo[i], c_lo[i]);

    P.kc = pr[0];  P.pctim = pr[1];  P.adimp = pr[2];
    P.uztwm = pr[3]; P.uzfwm = pr[4]; P.lztwm = pr[5];
    P.lzfsm = pr[6]; P.lzfpm = pr[7];
    P.pfree = pr[9]; P.riva = pr[10];
    P.zperc = pr[11]; P.rexp = pr[12]; P.uzk = pr[13];
    P.lzsk = pr[14]; P.lzpk = pr[15];
    P.ci = pr[16]; P.cgs = pr[17]; P.cgp = pr[18];
    float ke = pr[19], xe = pr[20];

    P.inv_uztwm    = 1.0f / P.uztwm;
    P.inv_sum_utlt = 1.0f / (P.uztwm + P.lztwm);
    P.inv_lztwm    = 1.0f / P.lztwm;
    P.sum_uzm      = P.uztwm + P.uzfwm;
    float pbase    = P.lzfsm * P.lzsk + P.lzfpm * P.lzpk;
    P.pbase_div_uzfwm = pbase / P.uzfwm;
    P.sum_lzm      = P.lzfsm + P.lzfpm + P.lztwm;
    P.inv_sum_lzm  = 1.0f / P.sum_lzm;
    P.sum_lzf      = P.lzfsm + P.lzfpm;
    P.cf2          = 2.0f * P.lzfpm / P.sum_lzf;
    P.inv_lzfpm    = 1.0f / P.lzfpm;
    P.inv_lzfsm    = 1.0f / P.lzfsm;
    P.parea        = 1.0f - P.pctim - P.adimp;
    P.omlzsk = 1.0f - P.lzsk;
    P.omlzpk = 1.0f - P.lzpk;
    P.gi  = (1.0f - P.ci)  * P.parea;
    P.ggs = (1.0f - P.cgs) * P.parea;
    P.ggp = (1.0f - P.cgp) * P.parea;
    const float dtm = 0.5f;
    float inv_denom = 1.0f / (ke * (1.0f - xe) + dtm);
    P.c1 = (ke * xe + dtm) * inv_denom;
    P.c2 = (dtm - ke * xe) * inv_denom;
    P.c3 = (ke * (1.0f - xe) - dtm) * inv_denom;
}

__device__ __forceinline__ void init_state(St& S) {
    S.auztw = S.alztw = S.uztw = S.uzfw = S.lztw = 0.01f;
    S.lzfs = S.lzfp = 0.01f;
    S.qs = S.qi = S.qgs = S.qgp = S.mq = 0.01f;
}

// One step (R4 body, proven correct: inactive clamps removed under state
// invariants 0<=state<=capacity, ep<=7.2<uztwm+lztwm; fmaxf(NaN,0)=0 does
// the nan_to_num).
__device__ __forceinline__ void sac_step(const Prm& P, St& S,
                                         float p_raw, float e_raw,
                                         float& o2_out, float& et_out) {
    float p = fmaxf(p_raw, 0.0f);
    float e = fmaxf(e_raw, 0.0f);
    float ep = P.kc * e;
    float roimp = P.pctim * p;
    float ae2 = P.pctim * ep;
    // ADIMP store
    float ae1 = fminf(S.auztw, ep * (S.auztw * P.inv_uztwm));
    float ae3 = (ep - ae1) * (S.alztw * P.inv_sum_utlt);
    float pav = fmaxf(p - (P.uztwm - (S.auztw - ae1)), 0.0f);
    float alz_ae3 = S.alztw - ae3;
    float adsur = pav * (alz_ae3 * P.inv_lztwm);
    float tmpA = pav - adsur + alz_ae3;
    float ars = fmaxf(tmpA - P.lztwm, 0.0f);
    S.auztw = fminf(P.uztwm, S.auztw - ae1 + p);
    S.alztw = fminf(P.lztwm, tmpA);
    // UZ evap
    float e1 = fminf(S.uztw, ep * (S.uztw * P.inv_uztwm));
    float e2 = fminf(S.uzfw, ep - e1);
    float e3 = (ep - e1 - e2) * (S.lztw * P.inv_sum_utlt);
    float lt1 = S.lztw - e3;
    float et = ae2 + ae1 + ae3 + e1 + e2 + e3 + P.riva * ep;
    // UZ balance
    float x = p + (S.uztw + S.uzfw - e1 - e2);
    float rs = fmaxf(x - P.sum_uzm, 0.0f) * P.parea;
    float ut = fminf(P.uztwm, S.uztw - e1 + p);
    float uf = fminf(P.uzfwm, x - ut);
    float ri = uf * P.uzk;
    uf = uf - ri;
    // percolation
    float ss = S.lzfs + S.lzfp + lt1;
    float defr = fmaxf(1.0f - ss * P.inv_sum_lzm, 0.0f);
    float perc = P.pbase_div_uzfwm * (1.0f + P.zperc * __powf(defr, P.rexp)) * uf;
    float rate = fminf(perc, P.sum_lzm - ss);
    uf = fmaxf(uf - rate, 0.0f);
    float fx = fminf(P.sum_lzf - (S.lzfs + S.lzfp),
                     fmaxf(rate - (P.lztwm - lt1), rate * P.pfree));
    float perct = rate - fx;
    float ca = 1.0f - S.lzfp * P.inv_lzfpm;
    float cb = 1.0f - S.lzfs * P.inv_lzfsm;
    float coef = fminf(P.cf2 * __fdividef(ca, ca + cb), 1.0f);
    float percp = fmaxf(fminf(P.lzfpm - S.lzfp,
                              fmaxf(fx - (P.lzfsm - S.lzfs), coef * fx)), 0.0f);
    float percs = fmaxf(fx - percp, 0.0f);
    // LZ update + decay
    float lt = fminf(lt1 + perct, P.lztwm);
    float ls = S.lzfs + percs;
    float lp = S.lzfp + percp;
    float rgs = ls * P.lzsk;
    float rgp = lp * P.lzpk;
    ls = ls * P.omlzsk;
    lp = lp * P.omlzpk;
    // routing
    float rs_tot = roimp + (adsur + ars) * P.adimp + rs;
    float i1 = S.qs + S.qi + S.qgs + S.qgp;
    S.qs  = rs_tot;
    S.qi  = P.ci  * S.qi  + P.gi  * ri;
    S.qgs = P.cgs * S.qgs + P.ggs * rgs;
    S.qgp = P.cgp * S.qgp + P.ggp * rgp;
    float i2 = S.qs + S.qi + S.qgs + S.qgp;
    float o2 = P.c1 * i1 + P.c2 * i2 + P.c3 * S.mq;
    S.mq = o2;
    S.uztw = ut; S.uzfw = uf; S.lztw = lt; S.lzfs = ls; S.lzfp = lp;
    o2_out = o2;
    et_out = et;
}

// Two basins per thread (independent chains interleave to fill issue slots
// during lat-4 RAW stalls) + PFD-deep register prefetch pipeline (keeps DRAM
// latency fully hidden — the combination R2 lacked).
__global__ void __launch_bounds__(128, 1) sac_kernel2(
    const float4* __restrict__ pe4,     // [T, B/2] of (p0,e0,p1,e1)
    const float*  __restrict__ raw,     // [B, 21]
    float*        __restrict__ out,     // [2, T-NWARM, B]
    int T, int B)
{
    int tid = blockIdx.x * blockDim.x + threadIdx.x;
    int half = B >> 1;                  // B even (10000)
    if (tid >= half) return;
    int b0 = 2 * tid;

    Prm P0, P1;
    load_prm(raw, b0, P0);
    load_prm(raw, b0 + 1, P1);

    St S0, S1;
    init_state(S0);
    init_state(S1);

    const int TOUT = T - NWARM;
    float* __restrict__ outQ = out;                       // [TOUT, B]
    float* __restrict__ outE = out + (size_t)TOUT * B;    // [TOUT, B]

    // register pipeline of future timesteps
    float4 buf[PFD];
#pragma unroll
    for (int d = 0; d < PFD; ++d) {
        int idx = d < T ? d : T - 1;
        buf[d] = __ldcs(&pe4[(size_t)idx * half + tid]);
    }

    int t = 0;
    for (; t + PFD <= T; t += PFD) {
#pragma unroll
        for (int j = 0; j < PFD; ++j) {
            int tl = t + j + PFD;
            float4 nxt = __ldcs(&pe4[(size_t)(tl < T ? tl : T - 1) * half + tid]);
            float o2a, eta, o2b, etb;
            sac_step(P0, S0, buf[j].x, buf[j].y, o2a, eta);
            sac_step(P1, S1, buf[j].z, buf[j].w, o2b, etb);
            int tt = t + j;
            if (tt >= NWARM) {
                size_t to = (size_t)(tt - NWARM) * B + b0;
                *(float2*)(outQ + to) = make_float2(o2a, o2b);
                *(float2*)(outE + to) = make_float2(eta, etb);
            }
            buf[j] = nxt;
        }
    }
#pragma unroll
    for (int j = 0; j < PFD; ++j) {
        int tt = t + j;
        if (tt < T) {
            float o2a, eta, o2b, etb;
            sac_step(P0, S0, buf[j].x, buf[j].y, o2a, eta);
            sac_step(P1, S1, buf[j].z, buf[j].w, o2b, etb);
            if (tt >= NWARM) {
                size_t to = (size_t)(tt - NWARM) * B + b0;
                *(float2*)(outQ + to) = make_float2(o2a, o2b);
                *(float2*)(outE + to) = make_float2(eta, etb);
            }
        }
    }
}

extern "C" void kernel_launch(void* const* d_in, const int* in_sizes, int n_in,
                              void* d_out, int out_size) {
    const float* pe     = (const float*)d_in[0];   // [T, B, 2] f32
    const float* params = (const float*)d_in[1];   // [B, 21]  f32
    int B = in_sizes[1] / 21;
    int T = in_sizes[0] / (2 * B);
    int half = B / 2;
    int threads = 128;
    int blocks = (half + threads - 1) / threads;
    sac_kernel2<<<blocks, threads>>>((const float4*)pe, params, (float*)d_out, T, B);
}

// round 12
// speedup vs baseline: 1.4270x; 1.4270x over previous
#include <cuda_runtime.h>

#define NWARM 365
#define PFD 8   // prefetch depth (register pipeline of future timesteps)

// PARAM_RANGES lo/hi, order: KC,PCTIM,ADIMP,UZTWM,UZFWM,LZTWM,LZFSM,LZFPM,RSERV,
// PFREE,RIVA,ZPERC,REXP,UZK,LZSK,LZPK,CI,CGS,CGP,KE,XE
__constant__ float c_lo[21] = {0.1f, 0.0f, 0.0f, 10.0f, 10.0f, 50.0f, 10.0f, 50.0f,
                               0.0f, 0.0f, 0.0f, 5.0f, 1.0f, 0.1f, 0.01f, 0.001f,
                               0.5f, 0.95f, 0.98f, 0.0f, 0.0f};
__constant__ float c_hi[21] = {1.2f, 0.1f, 0.3f, 100.0f, 100.0f, 400.0f, 100.0f, 1000.0f,
                               0.3f, 0.5f, 0.1f, 350.0f, 4.0f, 0.5f, 0.35f, 0.05f,
                               0.9f, 0.998f, 0.998f, 1.0f, 0.5f};

__global__ void __launch_bounds__(128, 1) sac_kernel(
    const float2* __restrict__ pe,      // [T, B] of (prcp, pet)
    const float*  __restrict__ raw,     // [B, 21] raw params in [0.01, 0.99]
    float*        __restrict__ out,     // [2, T-NWARM, B]
    int T, int B)
{
    int b = blockIdx.x * blockDim.x + threadIdx.x;
    if (b >= B) return;

    // ---- load + scale parameters ----
    float pr[21];
#pragma unroll
    for (int i = 0; i < 21; ++i)
        pr[i] = fmaf(raw[b * 21 + i], c_hi[i] - c_lo[i], c_lo[i]);

    const float kc = pr[0],  pctim = pr[1],  adimp = pr[2];
    const float uztwm = pr[3], uzfwm = pr[4], lztwm = pr[5];
    const float lzfsm = pr[6], lzfpm = pr[7];
    const float pfree = pr[9], riva = pr[10];
    const float zperc = pr[11], rexp = pr[12], uzk = pr[13];
    const float lzsk = pr[14], lzpk = pr[15];
    const float ci = pr[16], cgs = pr[17], cgp = pr[18];
    const float ke = pr[19], xe = pr[20];

    // ---- loop-invariant combos ----
    const float inv_uztwm    = 1.0f / uztwm;
    const float inv_sum_utlt = 1.0f / (uztwm + lztwm);
    const float inv_lztwm    = 1.0f / lztwm;
    const float sum_uzm      = uztwm + uzfwm;
    const float pbase        = lzfsm * lzsk + lzfpm * lzpk;
    const float sum_lzm      = lzfsm + lzfpm + lztwm;
    const float inv_sum_lzm  = 1.0f / sum_lzm;
    const float sum_lzf      = lzfsm + lzfpm;
    const float cf2          = 2.0f * lzfpm / sum_lzf;
    const float inv_lzfpm    = 1.0f / lzfpm;
    const float inv_lzfsm    = 1.0f / lzfsm;
    const float parea        = 1.0f - pctim - adimp;
    const float omlzsk = 1.0f - lzsk;
    const float omlzpk = 1.0f - lzpk;
    const float gi  = (1.0f - ci)  * parea;
    const float ggs = (1.0f - cgs) * parea;
    const float ggp = (1.0f - cgp) * parea;
    const float dtm   = 0.5f;
    const float inv_denom = 1.0f / (ke * (1.0f - xe) + dtm);
    const float c1 = (ke * xe + dtm) * inv_denom;
    const float c2 = (dtm - ke * xe) * inv_denom;
    const float c3 = (ke * (1.0f - xe) - dtm) * inv_denom;
    const float pbase_div_uzfwm = pbase / uzfwm;

    // ---- state ----
    float auztw = 0.01f, alztw = 0.01f, uztw = 0.01f, uzfw = 0.01f, lztw = 0.01f;
    float lzfs = 0.01f, lzfp = 0.01f;
    float qs = 0.01f, qi = 0.01f, qgs = 0.01f, qgp = 0.01f, mq = 0.01f;

    const int TOUT = T - NWARM;
    float* __restrict__ qp = out + b;                       // running [t][b] in outQ
    float* __restrict__ ep_ = out + (size_t)TOUT * B + b;   // running [t][b] in outE

    // One-step body (R4-proven simplifications). DO_STORE selects the
    // branch-free store variant. Loop-carried-only quantities (coef divide,
    // lz sums) are hoisted to the top so the RCP's 16-cycle latency is fully
    // off the critical path.
#define SAC_BODY(PEV, DO_STORE)                                                  \
    {                                                                            \
        /* early: depends only on prev-step state (ready at cycle 0) */          \
        float lzsum = lzfs + lzfp;                                               \
        float ca = 1.0f - lzfp * inv_lzfpm;                                      \
        float cb = 1.0f - lzfs * inv_lzfsm;                                      \
        float coef = fminf(cf2 * __fdividef(ca, ca + cb), 1.0f);                 \
        float avail_f = sum_lzf - lzsum;                                         \
        float free_p  = lzfpm - lzfp;                                            \
        float free_s  = lzfsm - lzfs;                                            \
        float uzsum = uztw + uzfw;                                               \
        /* input */                                                              \
        float p = fmaxf((PEV).x, 0.0f);                                          \
        float e = fmaxf((PEV).y, 0.0f);      /* fmaxf(NaN,0)=0 => nan_to_num */  \
        float ep = kc * e;                                                       \
        float roimp = pctim * p;                                                 \
        float ae2 = pctim * ep;                                                  \
        /* ADIMP store (independent subchain, only auztw/alztw carried) */       \
        float ae1 = fminf(auztw, ep * (auztw * inv_uztwm));                      \
        float ae3 = (ep - ae1) * (alztw * inv_sum_utlt);                         \
        float pav = fmaxf(p - (uztwm - (auztw - ae1)), 0.0f);                    \
        float alz_ae3 = alztw - ae3;                                             \
        float adsur = pav * (alz_ae3 * inv_lztwm);                               \
        float tmpA = pav - adsur + alz_ae3;                                      \
        float ars = fmaxf(tmpA - lztwm, 0.0f);                                   \
        auztw = fminf(uztwm, auztw - ae1 + p);                                   \
        alztw = fminf(lztwm, tmpA);                                              \
        /* UZ evap */                                                            \
        float e1 = fminf(uztw, ep * (uztw * inv_uztwm));                         \
        float e2 = fminf(uzfw, ep - e1);                                         \
        float e3 = (ep - e1 - e2) * (lztw * inv_sum_utlt);                       \
        float lt1 = lztw - e3;                                                   \
        float et = ((ae2 + ae1) + (ae3 + e1)) + ((e2 + e3) + riva * ep);         \
        /* UZ balance */                                                         \
        float x = p + (uzsum - e1 - e2);                                         \
        float rs = fmaxf(x - sum_uzm, 0.0f) * parea;                             \
        float ut = fminf(uztwm, uztw - e1 + p);                                  \
        float uf = fminf(uzfwm, x - ut);                                         \
        float ri = uf * uzk;                                                     \
        uf = uf - ri;                                                            \
        /* percolation */                                                        \
        float ss = lzsum + lt1;                                                  \
        float defr = fmaxf(fmaf(-ss, inv_sum_lzm, 1.0f), 0.0f);                  \
        float perc = pbase_div_uzfwm * fmaf(zperc, __powf(defr, rexp), 1.0f) * uf; \
        float rate = fminf(perc, sum_lzm - ss);                                  \
        uf = fmaxf(uf - rate, 0.0f);                                             \
        float fx = fminf(avail_f, fmaxf(rate - (lztwm - lt1), rate * pfree));    \
        float perct = rate - fx;                                                 \
        float percp = fmaxf(fminf(free_p, fmaxf(fx - free_s, coef * fx)), 0.0f); \
        float percs = fmaxf(fx - percp, 0.0f);                                   \
        /* LZ update + decay */                                                  \
        float lt = fminf(lt1 + perct, lztwm);                                    \
        float ls = lzfs + percs;                                                 \
        float lp = lzfp + percp;                                                 \
        float rgs = ls * lzsk;                                                   \
        float rgp = lp * lzpk;                                                   \
        ls = ls * omlzsk;                                                        \
        lp = lp * omlzpk;                                                        \
        /* routing */                                                            \
        float rs_tot = (roimp + rs) + (adsur + ars) * adimp;                     \
        float i1 = (qs + qi) + (qgs + qgp);                                      \
        qs  = rs_tot;                                                            \
        qi  = ci  * qi  + gi  * ri;                                              \
        qgs = cgs * qgs + ggs * rgs;                                             \
        qgp = cgp * qgp + ggp * rgp;                                             \
        float i2 = (qs + qi) + (qgs + qgp);                                      \
        float o2 = c1 * i1 + (c2 * i2 + c3 * mq);                                \
        mq = o2;                                                                 \
        uztw = ut; uzfw = uf; lztw = lt; lzfs = ls; lzfp = lp;                   \
        if (DO_STORE) {                                                          \
            __stcs(qp, o2);                                                      \
            __stcs(ep_, et);                                                     \
            qp += B; ep_ += B;                                                   \
        }                                                                        \
    }

    // ---- register pipeline: PFD timesteps in flight ----
    float2 buf[PFD];
#pragma unroll
    for (int d = 0; d < PFD; ++d) {
        int idx = d < T ? d : T - 1;
        buf[d] = __ldcs(&pe[(size_t)idx * B + b]);
    }

    // ---- warmup phase: t in [0, NWARM), no stores (NWARM=365 not nec. mult of PFD) ----
    int t = 0;
    for (; t + PFD <= NWARM; t += PFD) {
#pragma unroll
        for (int j = 0; j < PFD; ++j) {
            float2 nxt = __ldcs(&pe[(size_t)(t + j + PFD) * B + b]);  // t+j+PFD <= NWARM+PFD <= T
            SAC_BODY(buf[j], false);
            buf[j] = nxt;
        }
    }
    // warmup remainder + rotate buffer alignment into the output phase.
    // Handle the (NWARM - t) leftover steps one at a time with dynamic refill
    // via a small rotating index emulated by full-unroll + guard.
    {
        int rem = NWARM - t;   // 0..PFD-1 (365 = 45*8+5 -> rem=5)
#pragma unroll
        for (int j = 0; j < PFD; ++j) {
            if (j < rem) {
                int tl = t + j + PFD;
                float2 nxt = __ldcs(&pe[(size_t)(tl < T ? tl : T - 1) * B + b]);
                SAC_BODY(buf[j], false);
                buf[j] = nxt;
            }
        }
        // rotate buf so logical index 0 corresponds to t = NWARM
        float2 tmp[PFD];
#pragma unroll
        for (int j = 0; j < PFD; ++j) {
            int src = j + rem;
            tmp[j] = buf[src < PFD ? src : src - PFD];
        }
#pragma unroll
        for (int j = 0; j < PFD; ++j) buf[j] = tmp[j];
        t = NWARM;
    }

    // ---- output phase: t in [NWARM, T), always store, running pointers ----
    for (; t + PFD <= T; t += PFD) {
#pragma unroll
        for (int j = 0; j < PFD; ++j) {
            int tl = t + j + PFD;
            float2 nxt = __ldcs(&pe[(size_t)(tl < T ? tl : T - 1) * B + b]);
            SAC_BODY(buf[j], true);
            buf[j] = nxt;
        }
    }
#pragma unroll
    for (int j = 0; j < PFD; ++j) {
        if (t + j < T) {
            SAC_BODY(buf[j], true);
        }
    }
#undef SAC_BODY
}

extern "C" void kernel_launch(void* const* d_in, const int* in_sizes, int n_in,
                              void* d_out, int out_size) {
    const float* pe     = (const float*)d_in[0];   // [T, B, 2] f32
    const float* params = (const float*)d_in[1];   // [B, 21]  f32
    int B = in_sizes[1] / 21;
    int T = in_sizes[0] / (2 * B);
    int threads = 128;
    int blocks = (B + threads - 1) / threads;
    sac_kernel<<<blocks, threads>>>((const float2*)pe, params, (float*)d_out, T, B);
}

// round 13
// speedup vs baseline: 1.4428x; 1.0111x over previous
#include <cuda_runtime.h>

#define NWARM 365
#define PFD 8   // prefetch depth (register pipeline of future timesteps)

// PARAM_RANGES lo/hi, order: KC,PCTIM,ADIMP,UZTWM,UZFWM,LZTWM,LZFSM,LZFPM,RSERV,
// PFREE,RIVA,ZPERC,REXP,UZK,LZSK,LZPK,CI,CGS,CGP,KE,XE
__constant__ float c_lo[21] = {0.1f, 0.0f, 0.0f, 10.0f, 10.0f, 50.0f, 10.0f, 50.0f,
                               0.0f, 0.0f, 0.0f, 5.0f, 1.0f, 0.1f, 0.01f, 0.001f,
                               0.5f, 0.95f, 0.98f, 0.0f, 0.0f};
__constant__ float c_hi[21] = {1.2f, 0.1f, 0.3f, 100.0f, 100.0f, 400.0f, 100.0f, 1000.0f,
                               0.3f, 0.5f, 0.1f, 350.0f, 4.0f, 0.5f, 0.35f, 0.05f,
                               0.9f, 0.998f, 0.998f, 1.0f, 0.5f};

__global__ void __launch_bounds__(128, 1) sac_kernel(
    const float2* __restrict__ pe,      // [T, B] of (prcp, pet)
    const float*  __restrict__ raw,     // [B, 21] raw params in [0.01, 0.99]
    float*        __restrict__ out,     // [2, T-NWARM, B]
    int T, int B)
{
    int b = blockIdx.x * blockDim.x + threadIdx.x;
    if (b >= B) return;

    // ---- load + scale parameters ----
    float pr[21];
#pragma unroll
    for (int i = 0; i < 21; ++i)
        pr[i] = fmaf(raw[b * 21 + i], c_hi[i] - c_lo[i], c_lo[i]);

    const float kc = pr[0],  pctim = pr[1],  adimp = pr[2];
    const float uztwm = pr[3], uzfwm = pr[4], lztwm = pr[5];
    const float lzfsm = pr[6], lzfpm = pr[7];
    const float pfree = pr[9], riva = pr[10];
    const float zperc = pr[11], rexp = pr[12], uzk = pr[13];
    const float lzsk = pr[14], lzpk = pr[15];
    const float ci = pr[16], cgs = pr[17], cgp = pr[18];
    const float ke = pr[19], xe = pr[20];

    // ---- loop-invariant combos ----
    const float inv_uztwm    = 1.0f / uztwm;
    const float inv_sum_utlt = 1.0f / (uztwm + lztwm);
    const float inv_lztwm    = 1.0f / lztwm;
    const float sum_uzm      = uztwm + uzfwm;
    const float pbase        = lzfsm * lzsk + lzfpm * lzpk;
    const float sum_lzm      = lzfsm + lzfpm + lztwm;
    const float inv_sum_lzm  = 1.0f / sum_lzm;
    const float sum_lzf      = lzfsm + lzfpm;
    const float cf2          = 2.0f * lzfpm / sum_lzf;
    const float inv_lzfpm    = 1.0f / lzfpm;
    const float inv_lzfsm    = 1.0f / lzfsm;
    const float parea        = 1.0f - pctim - adimp;
    const float omlzsk = 1.0f - lzsk;
    const float omlzpk = 1.0f - lzpk;
    const float gi  = (1.0f - ci)  * parea;
    const float ggs = (1.0f - cgs) * parea;
    const float ggp = (1.0f - cgp) * parea;
    const float c_etep = pctim + riva;          // ae2 + e4 = (pctim+riva)*ep
    const float dtm   = 0.5f;
    const float inv_denom = 1.0f / (ke * (1.0f - xe) + dtm);
    const float c1 = (ke * xe + dtm) * inv_denom;
    const float c2 = (dtm - ke * xe) * inv_denom;
    const float c3 = (ke * (1.0f - xe) - dtm) * inv_denom;
    const float pbase_div_uzfwm = pbase / uzfwm;

    // ---- state ----
    float auztw = 0.01f, alztw = 0.01f, uztw = 0.01f, uzfw = 0.01f, lztw = 0.01f;
    float lzfs = 0.01f, lzfp = 0.01f;
    float qs = 0.01f, qi = 0.01f, qgs = 0.01f, qgp = 0.01f, mq = 0.01f;
    float isum = 0.04f;   // carried i2 = qs+qi+qgs+qgp of previous step

    const int TOUT = T - NWARM;
    float* __restrict__ qp  = out + b;                      // running [t][b] in outQ
    float* __restrict__ ep_ = out + (size_t)TOUT * B + b;   // running [t][b] in outE

    // One-step body. Proven simplifications:
    //  - ae1/e1 fminf dropped: ep <= 7.2 < uztwm_min=10 -> ep*inv_uztwm < 1
    //  - i1 = carried isum (previous step's i2)
    //  - defr = rate_cap * inv_sum_lzm, >= 0 by invariant ss <= sum_lzm
    //  - ep = fmaxf(kc*e_raw, 0) folds nan_to_num+relu+scale
#define SAC_BODY(PEV, DO_STORE)                                                  \
    {                                                                            \
        /* early: depends only on prev-step state (ready at cycle 0) */          \
        float lzsum = lzfs + lzfp;                                               \
        float ca = 1.0f - lzfp * inv_lzfpm;                                      \
        float cb = 1.0f - lzfs * inv_lzfsm;                                      \
        float coef = fminf(cf2 * __fdividef(ca, ca + cb), 1.0f);                 \
        float avail_f = sum_lzf - lzsum;                                         \
        float free_p  = lzfpm - lzfp;                                            \
        float free_s  = lzfsm - lzfs;                                            \
        /* input */                                                              \
        float p  = fmaxf((PEV).x, 0.0f);                                         \
        float ep = fmaxf(kc * (PEV).y, 0.0f);  /* fmaxf(NaN,0)=0 => nan_to_num */\
        float roimp = pctim * p;                                                 \
        /* ADIMP store */                                                        \
        float ae1 = ep * (auztw * inv_uztwm);          /* < auztw always */      \
        float ae3 = (ep - ae1) * (alztw * inv_sum_utlt);                         \
        float sA  = auztw - ae1 + p;                                             \
        float pav = fmaxf(sA - uztwm, 0.0f);                                     \
        float alz_ae3 = alztw - ae3;                                             \
        float adsur = pav * (alz_ae3 * inv_lztwm);                               \
        float tmpA = pav - adsur + alz_ae3;                                      \
        float ars = fmaxf(tmpA - lztwm, 0.0f);                                   \
        auztw = fminf(sA, uztwm);                                                \
        alztw = fminf(lztwm, tmpA);                                              \
        /* UZ evap */                                                            \
        float e1 = ep * (uztw * inv_uztwm);            /* < uztw always */       \
        float e2 = fminf(uzfw, ep - e1);                                         \
        float e3 = (ep - e1 - e2) * (lztw * inv_sum_utlt);                       \
        float lt1 = lztw - e3;                                                   \
        float et = (c_etep * ep + (ae1 + ae3)) + ((e1 + e2) + e3);               \
        /* UZ balance */                                                         \
        float sU = uztw - e1 + p;                                                \
        float x  = sU + (uzfw - e2);                                             \
        float rs = fmaxf(x - sum_uzm, 0.0f) * parea;                             \
        float ut = fminf(uztwm, sU);                                             \
        float uf = fminf(uzfwm, x - ut);                                         \
        float ri = uf * uzk;                                                     \
        uf = uf - ri;                                                            \
        /* percolation */                                                        \
        float ss = lzsum + lt1;                                                  \
        float rate_cap = sum_lzm - ss;                 /* >= 0 by invariant */   \
        float defr = rate_cap * inv_sum_lzm;                                     \
        float perc = pbase_div_uzfwm * fmaf(zperc, __powf(defr, rexp), 1.0f) * uf; \
        float rate = fminf(perc, rate_cap);                                      \
        uf = fmaxf(uf - rate, 0.0f);                                             \
        float fx = fminf(avail_f, fmaxf(rate - (lztwm - lt1), rate * pfree));    \
        float perct = rate - fx;                                                 \
        float percp = fmaxf(fminf(free_p, fmaxf(fx - free_s, coef * fx)), 0.0f); \
        float percs = fmaxf(fx - percp, 0.0f);                                   \
        /* LZ update + decay */                                                  \
        float lt = fminf(lt1 + perct, lztwm);                                    \
        float ls = lzfs + percs;                                                 \
        float lp = lzfp + percp;                                                 \
        float rgs = ls * lzsk;                                                   \
        float rgp = lp * lzpk;                                                   \
        ls = ls * omlzsk;                                                        \
        lp = lp * omlzpk;                                                        \
        /* routing: i1 = previous step's i2 (carried) */                         \
        float i1 = isum;                                                         \
        qs  = (roimp + rs) + (adsur + ars) * adimp;                              \
        qi  = ci  * qi  + gi  * ri;                                              \
        qgs = cgs * qgs + ggs * rgs;                                             \
        qgp = cgp * qgp + ggp * rgp;                                             \
        float i2 = (qs + qi) + (qgs + qgp);                                      \
        isum = i2;                                                               \
        float o2 = c1 * i1 + (c2 * i2 + c3 * mq);                                \
        mq = o2;                                                                 \
        uztw = ut; uzfw = uf; lztw = lt; lzfs = ls; lzfp = lp;                   \
        if (DO_STORE) {                                                          \
            __stcs(qp, o2);                                                      \
            __stcs(ep_, et);                                                     \
            qp += B; ep_ += B;                                                   \
        }                                                                        \
    }

    // ---- register pipeline: PFD timesteps in flight ----
    float2 buf[PFD];
#pragma unroll
    for (int d = 0; d < PFD; ++d) {
        int idx = d < T ? d : T - 1;
        buf[d] = __ldcs(&pe[(size_t)idx * B + b]);
    }
    // running prefetch pointer (tracks t + PFD; valid while t + PFD < T)
    const float2* __restrict__ pload = pe + (size_t)PFD * B + b;
    const size_t strideB = B;

    // ---- warmup phase: t in [0, NWARM), no stores ----
    // loads here reach at most NWARM+PFD-1 = 372 < T, always valid
    int t = 0;
    for (; t + PFD <= NWARM; t += PFD) {
#pragma unroll
        for (int j = 0; j < PFD; ++j) {
            float2 nxt = __ldcs(pload); pload += strideB;
            SAC_BODY(buf[j], false);
            buf[j] = nxt;
        }
    }
    {
        int rem = NWARM - t;   // 365 = 45*8+5 -> rem=5
#pragma unroll
        for (int j = 0; j < PFD; ++j) {
            if (j < rem) {
                float2 nxt = __ldcs(pload); pload += strideB;
                SAC_BODY(buf[j], false);
                buf[j] = nxt;
            }
        }
        // rotate buf so logical index 0 corresponds to t = NWARM
        float2 tmp[PFD];
#pragma unroll
        for (int j = 0; j < PFD; ++j) {
            int src = j + rem;
            tmp[j] = buf[src < PFD ? src : src - PFD];
        }
#pragma unroll
        for (int j = 0; j < PFD; ++j) buf[j] = tmp[j];
        t = NWARM;
    }

    // ---- output phase main: loads unconditionally valid while t+2*PFD <= T ----
    for (; t + 2 * PFD <= T; t += PFD) {
#pragma unroll
        for (int j = 0; j < PFD; ++j) {
            float2 nxt = __ldcs(pload); pload += strideB;
            SAC_BODY(buf[j], true);
            buf[j] = nxt;
        }
    }
    // penultimate chunk(s): clamped loads (at most one iteration)
    for (; t + PFD <= T; t += PFD) {
#pragma unroll
        for (int j = 0; j < PFD; ++j) {
            int tl = t + j + PFD;
            float2 nxt = __ldcs(&pe[(size_t)(tl < T ? tl : T - 1) * B + b]);
            SAC_BODY(buf[j], true);
            buf[j] = nxt;
        }
    }
    // guarded tail (< PFD steps)
#pragma unroll
    for (int j = 0; j < PFD; ++j) {
        if (t + j < T) {
            SAC_BODY(buf[j], true);
        }
    }
#undef SAC_BODY
}

extern "C" void kernel_launch(void* const* d_in, const int* in_sizes, int n_in,
                              void* d_out, int out_size) {
    const float* pe     = (const float*)d_in[0];   // [T, B, 2] f32
    const float* params = (const float*)d_in[1];   // [B, 21]  f32
    int B = in_sizes[1] / 21;
    int T = in_sizes[0] / (2 * B);
    int threads = 128;
    int blocks = (B + threads - 1) / threads;
    sac_kernel<<<blocks, threads>>>((const float2*)pe, params, (float*)d_out, T, B);
}

// round 14
// speedup vs baseline: 1.5282x; 1.0592x over previous
#include <cuda_runtime.h>

#define NWARM 365
#define PFD 8   // prefetch depth (register pipeline of future timesteps)

// PARAM_RANGES lo/hi, order: KC,PCTIM,ADIMP,UZTWM,UZFWM,LZTWM,LZFSM,LZFPM,RSERV,
// PFREE,RIVA,ZPERC,REXP,UZK,LZSK,LZPK,CI,CGS,CGP,KE,XE
__constant__ float c_lo[21] = {0.1f, 0.0f, 0.0f, 10.0f, 10.0f, 50.0f, 10.0f, 50.0f,
                               0.0f, 0.0f, 0.0f, 5.0f, 1.0f, 0.1f, 0.01f, 0.001f,
                               0.5f, 0.95f, 0.98f, 0.0f, 0.0f};
__constant__ float c_hi[21] = {1.2f, 0.1f, 0.3f, 100.0f, 100.0f, 400.0f, 100.0f, 1000.0f,
                               0.3f, 0.5f, 0.1f, 350.0f, 4.0f, 0.5f, 0.35f, 0.05f,
                               0.9f, 0.998f, 0.998f, 1.0f, 0.5f};

__device__ __forceinline__ float lg2_approx(float x) {
    float r;
    asm("lg2.approx.f32 %0, %1;" : "=f"(r) : "f"(x));
    return r;
}
__device__ __forceinline__ float ex2_approx(float x) {
    float r;
    asm("ex2.approx.f32 %0, %1;" : "=f"(r) : "f"(x));
    return r;
}

__global__ void __launch_bounds__(128, 1) sac_kernel(
    const float2* __restrict__ pe,      // [T, B] of (prcp, pet)
    const float*  __restrict__ raw,     // [B, 21] raw params in [0.01, 0.99]
    float*        __restrict__ out,     // [2, T-NWARM, B]
    int T, int B)
{
    int b = blockIdx.x * blockDim.x + threadIdx.x;
    if (b >= B) return;

    // ---- load + scale parameters ----
    float pr[21];
#pragma unroll
    for (int i = 0; i < 21; ++i)
        pr[i] = fmaf(raw[b * 21 + i], c_hi[i] - c_lo[i], c_lo[i]);

    const float kc = pr[0],  pctim = pr[1],  adimp = pr[2];
    const float uztwm = pr[3], uzfwm = pr[4], lztwm = pr[5];
    const float lzfsm = pr[6], lzfpm = pr[7];
    const float pfree = pr[9], riva = pr[10];
    const float zperc = pr[11], rexp = pr[12], uzk = pr[13];
    const float lzsk = pr[14], lzpk = pr[15];
    const float ci = pr[16], cgs = pr[17], cgp = pr[18];
    const float ke = pr[19], xe = pr[20];

    // ---- loop-invariant combos ----
    const float inv_uztwm    = 1.0f / uztwm;
    const float inv_sum_utlt = 1.0f / (uztwm + lztwm);
    const float inv_lztwm    = 1.0f / lztwm;
    const float sum_uzm      = uztwm + uzfwm;
    const float pbase        = lzfsm * lzsk + lzfpm * lzpk;
    const float sum_lzm      = lzfsm + lzfpm + lztwm;
    const float sum_lzf      = lzfsm + lzfpm;
    const float cf2          = 2.0f * lzfpm / sum_lzf;
    const float inv_lzfpm    = 1.0f / lzfpm;
    const float inv_lzfsm    = 1.0f / lzfsm;
    const float parea        = 1.0f - pctim - adimp;
    const float omlzsk = 1.0f - lzsk;
    const float omlzpk = 1.0f - lzpk;
    const float gi  = (1.0f - ci)  * parea;
    const float ggs = (1.0f - cgs) * parea;
    const float ggp = (1.0f - cgp) * parea;
    const float c_etep = pctim + riva;          // ae2 + e4 = (pctim+riva)*ep
    const float dtm   = 0.5f;
    const float inv_denom = 1.0f / (ke * (1.0f - xe) + dtm);
    const float c1 = (ke * xe + dtm) * inv_denom;
    const float c2 = (dtm - ke * xe) * inv_denom;
    const float c3 = (ke * (1.0f - xe) - dtm) * inv_denom;
    const float pbase_div_uzfwm = pbase / uzfwm;
    // exponent folding: 1 + zperc*defr^rexp, defr = rate_cap/sum_lzm
    //   => zperc*defr^rexp = ex2(rexp*lg2(rate_cap) + powbias)
    const float powbias = lg2_approx(zperc) - rexp * lg2_approx(sum_lzm);

    // ---- state (+ carried normalized copies, computed off the critical path) ----
    float auztw = 0.01f, alztw = 0.01f, uztw = 0.01f, uzfw = 0.01f, lztw = 0.01f;
    float lzfs = 0.01f, lzfp = 0.01f;
    float qs = 0.01f, qi = 0.01f, qgs = 0.01f, qgp = 0.01f, mq = 0.01f;
    float isum = 0.04f;   // carried i2 of previous step
    float au_n  = auztw * inv_uztwm;
    float alz_n = alztw * inv_sum_utlt;
    float ut_n  = uztw * inv_uztwm;
    float ltz_n = lztw * inv_sum_utlt;

    const int TOUT = T - NWARM;
    float* __restrict__ qp  = out + b;                      // running [t][b] in outQ
    float* __restrict__ ep_ = out + (size_t)TOUT * B + b;   // running [t][b] in outE

    // One-step body. Chain-shortening rewrites (all exact or <=1ulp):
    //  - e12 = min(uzfw+e1, ep) replaces dependent e2 min
    //  - pow folded: rate = min(fmaf(ex2(fmaf(rexp,lg2(rate_cap),powbias)),Cuf,Cuf), rate_cap)
    //  - percp outer max0 dead (coef>=0, fx>=0); percs max0 dead (percp<=fx)
    //  - lz decays folded into fmaf with early-computed bases
#define SAC_BODY(PEV, DO_STORE)                                                  \
    {                                                                            \
        /* early: prev-state-only (ready at cycle 0, off critical path) */       \
        float lzsum = lzfs + lzfp;                                               \
        float ca = 1.0f - lzfp * inv_lzfpm;                                      \
        float cb = 1.0f - lzfs * inv_lzfsm;                                      \
        float coef = fminf(cf2 * __fdividef(ca, ca + cb), 1.0f);                 \
        float avail_f = sum_lzf - lzsum;                                         \
        float free_p  = lzfpm - lzfp;                                            \
        float free_s  = lzfsm - lzfs;                                            \
        float m_rc    = sum_lzm - lzsum;                                         \
        float pre_ls_d = omlzsk * lzfs;                                          \
        float pre_lp_d = omlzpk * lzfp;                                          \
        float pre_ls_r = lzsk * lzfs;                                            \
        float pre_lp_r = lzpk * lzfp;                                            \
        /* input */                                                              \
        float p  = fmaxf((PEV).x, 0.0f);                                         \
        float ep = fmaxf(kc * (PEV).y, 0.0f);  /* fmaxf(NaN,0)=0 -> nan_to_num */\
        float roimp = pctim * p;                                                 \
        /* ADIMP store (short cycle) */                                          \
        float ae1 = ep * au_n;                                                   \
        float ae3 = (ep - ae1) * alz_n;                                          \
        float sA  = (auztw - ae1) + p;                                           \
        float pav = fmaxf(sA - uztwm, 0.0f);                                     \
        float alz_ae3 = alztw - ae3;                                             \
        float adsur = pav * (alz_ae3 * inv_lztwm);                               \
        float tmpA = pav - adsur + alz_ae3;                                      \
        float ars = fmaxf(tmpA - lztwm, 0.0f);                                   \
        auztw = fminf(sA, uztwm);                                                \
        alztw = fminf(lztwm, tmpA);                                              \
        au_n  = auztw * inv_uztwm;                                               \
        alz_n = alztw * inv_sum_utlt;                                            \
        /* UZ evap (front of the long chain) */                                  \
        float e1  = ep * ut_n;                                                   \
        float e12 = fminf(uzfw + e1, ep);   /* = e1 + e2 */                      \
        float e2  = e12 - e1;                                                    \
        float e3  = (ep - e12) * ltz_n;                                          \
        float lt1 = lztw - e3;                                                   \
        float et = (c_etep * ep + (ae1 + ae3)) + (e12 + e3);                     \
        /* UZ balance */                                                         \
        float sU = (uztw - e1) + p;                                              \
        float x  = sU + (uzfw - e2);                                             \
        float rs = fmaxf(x - sum_uzm, 0.0f) * parea;                             \
        float ut = fminf(uztwm, sU);                                             \
        float uf = fminf(uzfwm, x - ut);                                         \
        float ri = uf * uzk;                                                     \
        uf = uf - ri;                                                            \
        uztw = ut;                                                               \
        ut_n = ut * inv_uztwm;                                                   \
        /* percolation (critical chain) */                                       \
        float rate_cap = m_rc - lt1;              /* >= 0 by invariant */        \
        float lg   = lg2_approx(rate_cap);        /* lg2(0) = -inf -> pow 0 */   \
        float expo = fmaf(rexp, lg, powbias);                                    \
        float tpow = ex2_approx(expo);                                           \
        float Cuf  = pbase_div_uzfwm * uf;                                       \
        float rate = fminf(fmaf(tpow, Cuf, Cuf), rate_cap);                      \
        uf = fmaxf(uf - rate, 0.0f);                                             \
        uzfw = uf;                                                               \
        float fx = fminf(avail_f, fmaxf(rate - (lztwm - lt1), rate * pfree));    \
        float perct = rate - fx;                                                 \
        float percp = fminf(free_p, fmaxf(fx - free_s, coef * fx));              \
        float percs = fx - percp;                                                \
        /* LZ update + decay (folded) */                                         \
        float lt = fminf(lt1 + perct, lztwm);                                    \
        lztw  = lt;                                                              \
        ltz_n = lt * inv_sum_utlt;                                               \
        lzfs = fmaf(omlzsk, percs, pre_ls_d);                                    \
        lzfp = fmaf(omlzpk, percp, pre_lp_d);                                    \
        float rgs = fmaf(lzsk, percs, pre_ls_r);                                 \
        float rgp = fmaf(lzpk, percp, pre_lp_r);                                 \
        /* routing (short, off-chain) */                                         \
        float i1 = isum;                                                         \
        qs  = (roimp + rs) + (adsur + ars) * adimp;                              \
        qi  = ci  * qi  + gi  * ri;                                              \
        qgs = cgs * qgs + ggs * rgs;                                             \
        qgp = cgp * qgp + ggp * rgp;                                             \
        float i2 = (qs + qi) + (qgs + qgp);                                      \
        isum = i2;                                                               \
        float o2 = c1 * i1 + (c2 * i2 + c3 * mq);                                \
        mq = o2;                                                                 \
        if (DO_STORE) {                                                          \
            __stcs(qp, o2);                                                      \
            __stcs(ep_, et);                                                     \
            qp += B; ep_ += B;                                                   \
        }                                                                        \
    }

    // ---- register pipeline: PFD timesteps in flight ----
    float2 buf[PFD];
#pragma unroll
    for (int d = 0; d < PFD; ++d) {
        int idx = d < T ? d : T - 1;
        buf[d] = __ldcs(&pe[(size_t)idx * B + b]);
    }
    const float2* __restrict__ pload = pe + (size_t)PFD * B + b;
    const size_t strideB = B;

    // ---- warmup phase: t in [0, NWARM), no stores ----
    int t = 0;
    for (; t + PFD <= NWARM; t += PFD) {
#pragma unroll
        for (int j = 0; j < PFD; ++j) {
            float2 nxt = __ldcs(pload); pload += strideB;
            SAC_BODY(buf[j], false);
            buf[j] = nxt;
        }
    }
    {
        int rem = NWARM - t;   // 365 = 45*8+5 -> rem=5
#pragma unroll
        for (int j = 0; j < PFD; ++j) {
            if (j < rem) {
                float2 nxt = __ldcs(pload); pload += strideB;
                SAC_BODY(buf[j], false);
                buf[j] = nxt;
            }
        }
        float2 tmp[PFD];
#pragma unroll
        for (int j = 0; j < PFD; ++j) {
            int src = j + rem;
            tmp[j] = buf[src < PFD ? src : src - PFD];
        }
#pragma unroll
        for (int j = 0; j < PFD; ++j) buf[j] = tmp[j];
        t = NWARM;
    }

    // ---- output phase main: loads unconditionally valid while t+2*PFD <= T ----
    for (; t + 2 * PFD <= T; t += PFD) {
#pragma unroll
        for (int j = 0; j < PFD; ++j) {
            float2 nxt = __ldcs(pload); pload += strideB;
            SAC_BODY(buf[j], true);
            buf[j] = nxt;
        }
    }
    // penultimate chunk(s): clamped loads
    for (; t + PFD <= T; t += PFD) {
#pragma unroll
        for (int j = 0; j < PFD; ++j) {
            int tl = t + j + PFD;
            float2 nxt = __ldcs(&pe[(size_t)(tl < T ? tl : T - 1) * B + b]);
            SAC_BODY(buf[j], true);
            buf[j] = nxt;
        }
    }
    // guarded tail (< PFD steps)
#pragma unroll
    for (int j = 0; j < PFD; ++j) {
        if (t + j < T) {
            SAC_BODY(buf[j], true);
        }
    }
#undef SAC_BODY
}

extern "C" void kernel_launch(void* const* d_in, const int* in_sizes, int n_in,
                              void* d_out, int out_size) {
    const float* pe     = (const float*)d_in[0];   // [T, B, 2] f32
    const float* params = (const float*)d_in[1];   // [B, 21]  f32
    int B = in_sizes[1] / 21;
    int T = in_sizes[0] / (2 * B);
    int threads = 128;
    int blocks = (B + threads - 1) / threads;
    sac_kernel<<<blocks, threads>>>((const float2*)pe, params, (float*)d_out, T, B);
}